// round 16
// baseline (speedup 1.0000x reference)
#include <cuda_runtime.h>

// Embedding gather: out[row, :] = weight[ids[row], :]
// ids: [8192] int32, weight: [32000, 1024] f32, out: [8192, 1024] f32.
//
// FINAL — best measured: 10.688us. Eight structural variants bracket a hard
// ~10.7us floor for this pattern (64MB compulsory read+write traffic):
//   - LSU float4, 1 CTA/row ............ 10.69-10.75us  <-- this kernel
//   - MLP=8 row batching ............... 10.98us (neutral)
//   - TMA cp.async.bulk (2 shapes) ..... 10.98 / 11.26us (neutral)
//   - write-through stores ............. 10.72us (neutral, kept: no downside)
//   - L2 evict_last (3 encodings) ...... neutral or worse; L2 does not
//     retain either stream across graph replays
//   - LDG.256 (v8.b32) ................. 15.1us (L1tex replay penalty; trap)
//
// Structure: one CTA per output row; 256 threads x float4 = one 1024-float
// row. Fully coalesced 128B lines both directions; __stwt avoids dirty-line
// churn for the never-re-read output.

#define DIM 1024
#define VEC (DIM / 4)   // 256 float4 per row

__global__ void __launch_bounds__(256, 8)
embed_gather_kernel(const int* __restrict__ ids,
                    const float* __restrict__ weight,
                    float* __restrict__ out)
{
    const int row = blockIdx.x;
    const int id  = __ldg(ids + row);

    const float4* __restrict__ src =
        reinterpret_cast<const float4*>(weight) + (size_t)id * VEC;
    float4* __restrict__ dst =
        reinterpret_cast<float4*>(out) + (size_t)row * VEC;

    const float4 v = __ldg(src + threadIdx.x);
    __stwt(dst + threadIdx.x, v);
}

extern "C" void kernel_launch(void* const* d_in, const int* in_sizes, int n_in,
                              void* d_out, int out_size)
{
    // metadata order: input_ids (int32, 4*2048), weight (float32, 32000*1024)
    const int*   ids    = (const int*)d_in[0];
    const float* weight = (const float*)d_in[1];
    float*       out    = (float*)d_out;

    const int n_rows = in_sizes[0];   // 8192

    embed_gather_kernel<<<n_rows, 256>>>(ids, weight, out);
}

// round 17
// speedup vs baseline: 1.0269x; 1.0269x over previous
#include <cuda_runtime.h>

// Embedding gather: out[row, :] = weight[ids[row], :]
// ids: [8192] int32, weight: [32000, 1024] f32, out: [8192, 1024] f32.
//
// FINAL — best measured: 10.688us (run-to-run noise band ±0.3us, confirmed
// by re-measuring this exact binary: 10.69 / 10.72 / 11.01us).
//
// Floor accounting: 32MB gathered weight reads (steady-state L2 hits) +
// 32MB compulsory output writes (DRAM stream, ~2.4TB/s measured) pace the
// kernel; no pipe exceeds 30% SOL and no structural variant moved the time:
//   - MLP=8 row batching ............... neutral
//   - TMA cp.async.bulk (2 shapes) ..... neutral
//   - write-through / policy stores .... neutral
//   - L2 evict_last (3 encodings) ...... neutral (L2 retains neither stream
//     across graph replays) 
//   - LDG.256 (v8.b32) ................. 15.1us — L1tex replay trap
//   - grid/block shapes 1024..8192 ..... neutral
//
// Structure: one CTA per output row; 256 threads x float4 = one 1024-float
// row. Fully coalesced 128B lines both directions; __stwt keeps the
// never-re-read output from churning L2 dirty lines.

#define DIM 1024
#define VEC (DIM / 4)   // 256 float4 per row

__global__ void __launch_bounds__(256, 8)
embed_gather_kernel(const int* __restrict__ ids,
                    const float* __restrict__ weight,
                    float* __restrict__ out)
{
    const int row = blockIdx.x;
    const int id  = __ldg(ids + row);

    const float4* __restrict__ src =
        reinterpret_cast<const float4*>(weight) + (size_t)id * VEC;
    float4* __restrict__ dst =
        reinterpret_cast<float4*>(out) + (size_t)row * VEC;

    const float4 v = __ldg(src + threadIdx.x);
    __stwt(dst + threadIdx.x, v);
}

extern "C" void kernel_launch(void* const* d_in, const int* in_sizes, int n_in,
                              void* d_out, int out_size)
{
    // metadata order: input_ids (int32, 4*2048), weight (float32, 32000*1024)
    const int*   ids    = (const int*)d_in[0];
    const float* weight = (const float*)d_in[1];
    float*       out    = (float*)d_out;

    const int n_rows = in_sizes[0];   // 8192

    embed_gather_kernel<<<n_rows, 256>>>(ids, weight, out);
}